// round 16
// baseline (speedup 1.0000x reference)
#include <cuda_runtime.h>
#include <cstdint>

// Problem constants (fixed by the dataset)
#define KMAX      24    // max n-grams per word
#define ROW_BYTES 512   // E=128 fp32

// Zero row for the odd trailing slot when cnt is odd (padded id 0 -> zero
// contribution; raw table row 0 is NOT zero, reference zeroes it).
__device__ __align__(256) float g_zero_row[128];

// 256-bit table gather, L2 evict_last (keep the 102MB table resident in the
// 126MB L2 across graph replays).
__device__ __forceinline__ void ldg256_evl(const void* p, uint64_t d[4]) {
    asm("ld.global.nc.L2::evict_last.v4.b64 {%0,%1,%2,%3}, [%4];"
        : "=l"(d[0]), "=l"(d[1]), "=l"(d[2]), "=l"(d[3])
        : "l"(p));
}

// Output store: WRITE-THROUGH, no L2 allocation. The 16.8MB output stream
// must not churn L2 line allocations (even evict_first allocates
// transiently) — the table needs every L2 set it can get. Single-variable
// change vs the 25.09us evict_first kernel.
__device__ __forceinline__ void stg256_wt(void* p, const uint64_t d[4]) {
    asm volatile("st.global.wt.v4.b64 [%0], {%1,%2,%3,%4};"
                 :: "l"(p), "l"(d[0]), "l"(d[1]), "l"(d[2]), "l"(d[3])
                 : "memory");
}

// word_idx:      [B*S]      int32
// ngram_ids:     [V, 24]    int32   (slot >= count padded with 0)
// ngram_counts:  [V]        int32
// emb_table:     [NG, 128]  float32
// out:           [B*S, 128] float32 = mean over valid ngram embeddings
//
// TWO words per warp, both prologues issued up front (B's prologue latency
// hides behind A's gathers). Each LDG.256 fetches two ngram rows (lanes
// 0-15 even slot, 16-31 odd slot); warp-uniform trip count ceil(cnt/2).
__global__ __launch_bounds__(256)
void ngram_emb_kernel(const int* __restrict__ word_idx,
                      const int* __restrict__ ngram_ids,
                      const int* __restrict__ ngram_counts,
                      const char* __restrict__ emb,    // byte view of table
                      char* __restrict__ out,          // byte view of output
                      int n_words) {
    const int warp = (blockIdx.x * blockDim.x + threadIdx.x) >> 5;
    const int lane = threadIdx.x & 31;

    const int posA = warp * 2;
    const int posB = posA + 1;
    if (posA >= n_words) return;
    const bool hasB = (posB < n_words);

    const int half = lane >> 4;       // 0: even slots, 1: odd slots
    const int sub  = lane & 15;       // 32B chunk within the 512B row
    const char* zrow = (const char*)g_zero_row + sub * 32;

    // ---- both prologues in flight together -----------------------------
    const int wA = __ldg(&word_idx[posA]);
    const int wB = hasB ? __ldg(&word_idx[posB]) : wA;

    int idA = 0, idB = 0;
    if (lane < KMAX) {
        idA = __ldg(&ngram_ids[wA * KMAX + lane]);
        idB = __ldg(&ngram_ids[wB * KMAX + lane]);
    }
    const int cntA = __ldg(&ngram_counts[wA]);
    const int cntB = __ldg(&ngram_counts[wB]);
    const int pairsA = (cntA + 1) >> 1;   // warp-uniform trip counts
    const int pairsB = (cntB + 1) >> 1;

    // ---- word A ---------------------------------------------------------
    float acc[8];
    #pragma unroll
    for (int i = 0; i < 8; ++i) acc[i] = 0.f;

    #pragma unroll
    for (int t = 0; t < KMAX / 2; ++t) {
        if (t >= pairsA) break;         // warp-uniform: no divergence
        const int id = __shfl_sync(0xffffffffu, idA, 2 * t + half);
        const void* p = id ? (const void*)(emb + (size_t)id * ROW_BYTES + sub * 32)
                           : (const void*)zrow;
        uint64_t d[4];
        ldg256_evl(p, d);
        #pragma unroll
        for (int i = 0; i < 4; ++i) {
            acc[2 * i + 0] += __uint_as_float((uint32_t)d[i]);
            acc[2 * i + 1] += __uint_as_float((uint32_t)(d[i] >> 32));
        }
    }

    #pragma unroll
    for (int i = 0; i < 8; ++i)
        acc[i] += __shfl_xor_sync(0xffffffffu, acc[i], 16);

    {
        const float inv = 1.0f / (float)cntA;
        if (half == 0) {
            uint64_t q[4];
            #pragma unroll
            for (int i = 0; i < 4; ++i) {
                const uint32_t lo = __float_as_uint(acc[2 * i + 0] * inv);
                const uint32_t hi = __float_as_uint(acc[2 * i + 1] * inv);
                q[i] = (uint64_t)lo | ((uint64_t)hi << 32);
            }
            stg256_wt(out + (size_t)posA * ROW_BYTES + sub * 32, q);
        }
    }

    // ---- word B ---------------------------------------------------------
    if (!hasB) return;

    #pragma unroll
    for (int i = 0; i < 8; ++i) acc[i] = 0.f;

    #pragma unroll
    for (int t = 0; t < KMAX / 2; ++t) {
        if (t >= pairsB) break;         // warp-uniform: no divergence
        const int id = __shfl_sync(0xffffffffu, idB, 2 * t + half);
        const void* p = id ? (const void*)(emb + (size_t)id * ROW_BYTES + sub * 32)
                           : (const void*)zrow;
        uint64_t d[4];
        ldg256_evl(p, d);
        #pragma unroll
        for (int i = 0; i < 4; ++i) {
            acc[2 * i + 0] += __uint_as_float((uint32_t)d[i]);
            acc[2 * i + 1] += __uint_as_float((uint32_t)(d[i] >> 32));
        }
    }

    #pragma unroll
    for (int i = 0; i < 8; ++i)
        acc[i] += __shfl_xor_sync(0xffffffffu, acc[i], 16);

    {
        const float inv = 1.0f / (float)cntB;
        if (half == 0) {
            uint64_t q[4];
            #pragma unroll
            for (int i = 0; i < 4; ++i) {
                const uint32_t lo = __float_as_uint(acc[2 * i + 0] * inv);
                const uint32_t hi = __float_as_uint(acc[2 * i + 1] * inv);
                q[i] = (uint64_t)lo | ((uint64_t)hi << 32);
            }
            stg256_wt(out + (size_t)posB * ROW_BYTES + sub * 32, q);
        }
    }
}

extern "C" void kernel_launch(void* const* d_in, const int* in_sizes, int n_in,
                              void* d_out, int out_size) {
    const int*   word_idx     = (const int*)d_in[0];   // [B*S]
    const int*   ngram_ids    = (const int*)d_in[1];   // [V*24]
    const int*   ngram_counts = (const int*)d_in[2];   // [V]
    const char*  emb_table    = (const char*)d_in[3];  // [NG*128] f32
    char*        outp         = (char*)d_out;

    const int n_words = in_sizes[0];                   // 32768
    const int n_warps = (n_words + 1) / 2;             // 2 words per warp
    const int threads = 256;                           // 8 warps / block
    const int warps_per_block = threads / 32;
    const int blocks = (n_warps + warps_per_block - 1) / warps_per_block;

    ngram_emb_kernel<<<blocks, threads>>>(word_idx, ngram_ids, ngram_counts,
                                          emb_table, outp, n_words);
}